// round 6
// baseline (speedup 1.0000x reference)
#include <cuda_runtime.h>
#include <cuda_bf16.h>
#include <math.h>

// ---------------- intermediate buffers (device globals; no allocation) ------
__device__ float g_a1[128 * 32 * 56 * 56];   // conv1 out
__device__ float g_a2[128 * 64 * 28 * 28];   // conv2 out
__device__ float g_a3[128 * 128 * 14 * 14];  // conv3 out
__device__ float g_feat[128 * 512];          // pooled features

// pre-split weights (tf32 hi/lo), layout [k][oc]
__device__ unsigned int g_w1h[160 * 32],  g_w1l[160 * 32];    // K padded 147->160
__device__ unsigned int g_w2h[288 * 64],  g_w2l[288 * 64];
__device__ unsigned int g_w3h[576 * 128], g_w3l[576 * 128];

// ---------------- helpers ---------------------------------------------------
__device__ __forceinline__ void tf32split(float v, unsigned int& h, unsigned int& l) {
    asm("cvt.rna.tf32.f32 %0, %1;" : "=r"(h) : "f"(v));
    float r = v - __uint_as_float(h);
    asm("cvt.rna.tf32.f32 %0, %1;" : "=r"(l) : "f"(r));
}

#define MMA(d, A0, A1, A2, A3, B0, B1)                                          \
    asm volatile(                                                               \
        "mma.sync.aligned.m16n8k8.row.col.f32.tf32.tf32.f32 "                   \
        "{%0,%1,%2,%3}, {%4,%5,%6,%7}, {%8,%9}, {%0,%1,%2,%3};"                 \
        : "+f"(d[0]), "+f"(d[1]), "+f"(d[2]), "+f"(d[3])                        \
        : "r"(A0), "r"(A1), "r"(A2), "r"(A3), "r"(B0), "r"(B1))

// ---------------- weight prep: fp32 -> tf32 hi/lo, [oc][K] -> [K][oc] -------
__global__ void prep_w(const float* __restrict__ w1, const float* __restrict__ w2,
                       const float* __restrict__ w3) {
    int i = blockIdx.x * 256 + threadIdx.x;
    if (i < 160 * 32) {
        int k = i >> 5, oc = i & 31;
        float v = (k < 147) ? w1[oc * 147 + k] : 0.f;
        tf32split(v, g_w1h[i], g_w1l[i]);
    }
    if (i < 288 * 64) {
        int k = i >> 6, oc = i & 63;
        tf32split(w2[oc * 288 + k], g_w2h[i], g_w2l[i]);
    }
    if (i < 576 * 128) {
        int k = i >> 7, oc = i & 127;
        tf32split(w3[oc * 576 + k], g_w3h[i], g_w3l[i]);
    }
}

// ---------------- conv1: 3->32, 7x7 s4 p3, 224->56 (GEMM 32 x 3136 x 147) ---
__global__ void conv1_mma(const float* __restrict__ x,
                          const float* __restrict__ bg, const float* __restrict__ bb,
                          const float* __restrict__ bm, const float* __restrict__ bv,
                          const float* __restrict__ cb) {
    __shared__ unsigned int sAh[32 * 40], sAl[32 * 40];  // [k][oc] pad 40
    __shared__ unsigned int sBh[32 * 72], sBl[32 * 72];  // [k][px] pad 72
    const int tid = threadIdx.x;
    const int b = blockIdx.y;
    const int pxt = blockIdx.x * 64;
    const int wid = tid >> 5, lane = tid & 31;
    const int gid = lane >> 2, tig = lane & 3;
    const int ocb = (wid & 1) * 16;
    const int pxw = (wid >> 1) * 32;

    float acc[4][4];
#pragma unroll
    for (int n = 0; n < 4; n++)
#pragma unroll
        for (int j = 0; j < 4; j++) acc[n][j] = 0.f;

    const int pxl = tid & 63;
    const int pxg = pxt + pxl;
    const int oh = pxg / 56, ow = pxg % 56;

    for (int chunk = 0; chunk < 5; chunk++) {
        int kc = chunk * 32;
        __syncthreads();
        // A gather: 1024 elems
#pragma unroll
        for (int i = 0; i < 8; i++) {
            int e = tid + i * 128;
            int oc = e & 31, k = e >> 5;
            sAh[k * 40 + oc] = g_w1h[(kc + k) * 32 + oc];
            sAl[k * 40 + oc] = g_w1l[(kc + k) * 32 + oc];
        }
        // B gather (im2col): 2048 elems; fixed px per thread
#pragma unroll
        for (int i = 0; i < 16; i++) {
            int kl = (tid >> 6) + 2 * i;
            int k = kc + kl;
            float v = 0.f;
            if (k < 147) {
                int ic = k / 49, r = k % 49, kh = r / 7, kw = r % 7;
                int ih = oh * 4 - 3 + kh, iw = ow * 4 - 3 + kw;
                if ((unsigned)ih < 224u && (unsigned)iw < 224u)
                    v = __ldg(x + ((size_t)(b * 3 + ic) * 224 + ih) * 224 + iw);
            }
            unsigned int h, l;
            tf32split(v, h, l);
            sBh[kl * 72 + pxl] = h;
            sBl[kl * 72 + pxl] = l;
        }
        __syncthreads();
#pragma unroll
        for (int ks = 0; ks < 4; ks++) {
            int kr = ks * 8;
            unsigned int ah0 = sAh[(kr + tig) * 40 + ocb + gid];
            unsigned int ah1 = sAh[(kr + tig) * 40 + ocb + gid + 8];
            unsigned int ah2 = sAh[(kr + tig + 4) * 40 + ocb + gid];
            unsigned int ah3 = sAh[(kr + tig + 4) * 40 + ocb + gid + 8];
            unsigned int al0 = sAl[(kr + tig) * 40 + ocb + gid];
            unsigned int al1 = sAl[(kr + tig) * 40 + ocb + gid + 8];
            unsigned int al2 = sAl[(kr + tig + 4) * 40 + ocb + gid];
            unsigned int al3 = sAl[(kr + tig + 4) * 40 + ocb + gid + 8];
#pragma unroll
            for (int nf = 0; nf < 4; nf++) {
                int col = pxw + nf * 8 + gid;
                unsigned int bh0 = sBh[(kr + tig) * 72 + col];
                unsigned int bh1 = sBh[(kr + tig + 4) * 72 + col];
                unsigned int bl0 = sBl[(kr + tig) * 72 + col];
                unsigned int bl1 = sBl[(kr + tig + 4) * 72 + col];
                MMA(acc[nf], ah0, ah1, ah2, ah3, bh0, bh1);
                MMA(acc[nf], ah0, ah1, ah2, ah3, bl0, bl1);
                MMA(acc[nf], al0, al1, al2, al3, bh0, bh1);
            }
        }
    }
    // epilogue: BN + ReLU, rows r0 = ocb+gid, r1 = r0+8
    int r0 = ocb + gid, r1 = r0 + 8;
    float s0 = bg[r0] * rsqrtf(bv[r0] + 1e-5f);
    float h0 = (cb[r0] - bm[r0]) * s0 + bb[r0];
    float s1 = bg[r1] * rsqrtf(bv[r1] + 1e-5f);
    float h1 = (cb[r1] - bm[r1]) * s1 + bb[r1];
    float* o0 = g_a1 + ((size_t)b * 32 + r0) * 3136;
    float* o1 = g_a1 + ((size_t)b * 32 + r1) * 3136;
#pragma unroll
    for (int nf = 0; nf < 4; nf++) {
        int col = pxt + pxw + nf * 8 + 2 * tig;
        float2 v0 = make_float2(fmaxf(acc[nf][0] * s0 + h0, 0.f),
                                fmaxf(acc[nf][1] * s0 + h0, 0.f));
        float2 v1 = make_float2(fmaxf(acc[nf][2] * s1 + h1, 0.f),
                                fmaxf(acc[nf][3] * s1 + h1, 0.f));
        *reinterpret_cast<float2*>(o0 + col) = v0;
        *reinterpret_cast<float2*>(o1 + col) = v1;
    }
}

// ---------------- conv2: 32->64, 3x3 s2 p1, 56->28 (GEMM 64 x 784 x 288) ----
__global__ void conv2_mma(const float* __restrict__ bg, const float* __restrict__ bb,
                          const float* __restrict__ bm, const float* __restrict__ bv,
                          const float* __restrict__ cb) {
    __shared__ unsigned int sAh[32 * 72], sAl[32 * 72];  // [k][oc] pad 72
    __shared__ unsigned int sBh[32 * 72], sBl[32 * 72];  // [k][px] pad 72
    const int tid = threadIdx.x;
    const int b = blockIdx.y;
    const int pxt = blockIdx.x * 64;
    const int wid = tid >> 5, lane = tid & 31;
    const int gid = lane >> 2, tig = lane & 3;
    const int ocb = wid * 16;

    float acc[8][4];
#pragma unroll
    for (int n = 0; n < 8; n++)
#pragma unroll
        for (int j = 0; j < 4; j++) acc[n][j] = 0.f;

    const int pxl = tid & 63;
    const int pxg = pxt + pxl;
    const int oh = pxg / 28, ow = pxg % 28;
    const float* inb = g_a1 + (size_t)b * 32 * 3136;

    for (int chunk = 0; chunk < 9; chunk++) {
        int kc = chunk * 32;
        __syncthreads();
#pragma unroll
        for (int i = 0; i < 16; i++) {
            int e = tid + i * 128;
            int oc = e & 63, k = e >> 6;
            sAh[k * 72 + oc] = g_w2h[(kc + k) * 64 + oc];
            sAl[k * 72 + oc] = g_w2l[(kc + k) * 64 + oc];
        }
#pragma unroll
        for (int i = 0; i < 16; i++) {
            int kl = (tid >> 6) + 2 * i;
            int k = kc + kl;
            int ic = k / 9, t = k % 9, kh = t / 3, kw = t % 3;
            int ih = oh * 2 - 1 + kh, iw = ow * 2 - 1 + kw;
            float v = 0.f;
            if (pxg < 784 && (unsigned)ih < 56u && (unsigned)iw < 56u)
                v = __ldg(inb + (size_t)ic * 3136 + ih * 56 + iw);
            unsigned int h, l;
            tf32split(v, h, l);
            sBh[kl * 72 + pxl] = h;
            sBl[kl * 72 + pxl] = l;
        }
        __syncthreads();
#pragma unroll
        for (int ks = 0; ks < 4; ks++) {
            int kr = ks * 8;
            unsigned int ah0 = sAh[(kr + tig) * 72 + ocb + gid];
            unsigned int ah1 = sAh[(kr + tig) * 72 + ocb + gid + 8];
            unsigned int ah2 = sAh[(kr + tig + 4) * 72 + ocb + gid];
            unsigned int ah3 = sAh[(kr + tig + 4) * 72 + ocb + gid + 8];
            unsigned int al0 = sAl[(kr + tig) * 72 + ocb + gid];
            unsigned int al1 = sAl[(kr + tig) * 72 + ocb + gid + 8];
            unsigned int al2 = sAl[(kr + tig + 4) * 72 + ocb + gid];
            unsigned int al3 = sAl[(kr + tig + 4) * 72 + ocb + gid + 8];
#pragma unroll
            for (int nf = 0; nf < 8; nf++) {
                int col = nf * 8 + gid;
                unsigned int bh0 = sBh[(kr + tig) * 72 + col];
                unsigned int bh1 = sBh[(kr + tig + 4) * 72 + col];
                unsigned int bl0 = sBl[(kr + tig) * 72 + col];
                unsigned int bl1 = sBl[(kr + tig + 4) * 72 + col];
                MMA(acc[nf], ah0, ah1, ah2, ah3, bh0, bh1);
                MMA(acc[nf], ah0, ah1, ah2, ah3, bl0, bl1);
                MMA(acc[nf], al0, al1, al2, al3, bh0, bh1);
            }
        }
    }
    int r0 = ocb + gid, r1 = r0 + 8;
    float s0 = bg[r0] * rsqrtf(bv[r0] + 1e-5f);
    float h0 = (cb[r0] - bm[r0]) * s0 + bb[r0];
    float s1 = bg[r1] * rsqrtf(bv[r1] + 1e-5f);
    float h1 = (cb[r1] - bm[r1]) * s1 + bb[r1];
    float* o0 = g_a2 + ((size_t)b * 64 + r0) * 784;
    float* o1 = g_a2 + ((size_t)b * 64 + r1) * 784;
#pragma unroll
    for (int nf = 0; nf < 8; nf++) {
        int col = pxt + nf * 8 + 2 * tig;
        if (col + 1 < 784) {
            float2 v0 = make_float2(fmaxf(acc[nf][0] * s0 + h0, 0.f),
                                    fmaxf(acc[nf][1] * s0 + h0, 0.f));
            float2 v1 = make_float2(fmaxf(acc[nf][2] * s1 + h1, 0.f),
                                    fmaxf(acc[nf][3] * s1 + h1, 0.f));
            *reinterpret_cast<float2*>(o0 + col) = v0;
            *reinterpret_cast<float2*>(o1 + col) = v1;
        }
    }
}

// ---------------- conv3: 64->128, 3x3 s2 p1, 28->14 (GEMM 128 x 196 x 576) --
__global__ void conv3_mma(const float* __restrict__ bg, const float* __restrict__ bb,
                          const float* __restrict__ bm, const float* __restrict__ bv,
                          const float* __restrict__ cb) {
    __shared__ unsigned int sAh[32 * 72], sAl[32 * 72];
    __shared__ unsigned int sBh[32 * 72], sBl[32 * 72];
    const int tid = threadIdx.x;
    const int b = blockIdx.y;
    const int pxt = blockIdx.x * 64;
    const int ocz = blockIdx.z * 64;
    const int wid = tid >> 5, lane = tid & 31;
    const int gid = lane >> 2, tig = lane & 3;
    const int ocb = wid * 16;

    float acc[8][4];
#pragma unroll
    for (int n = 0; n < 8; n++)
#pragma unroll
        for (int j = 0; j < 4; j++) acc[n][j] = 0.f;

    const int pxl = tid & 63;
    const int pxg = pxt + pxl;
    const int oh = pxg / 14, ow = pxg % 14;
    const float* inb = g_a2 + (size_t)b * 64 * 784;

    for (int chunk = 0; chunk < 18; chunk++) {
        int kc = chunk * 32;
        __syncthreads();
#pragma unroll
        for (int i = 0; i < 16; i++) {
            int e = tid + i * 128;
            int oc = e & 63, k = e >> 6;
            sAh[k * 72 + oc] = g_w3h[(kc + k) * 128 + ocz + oc];
            sAl[k * 72 + oc] = g_w3l[(kc + k) * 128 + ocz + oc];
        }
#pragma unroll
        for (int i = 0; i < 16; i++) {
            int kl = (tid >> 6) + 2 * i;
            int k = kc + kl;
            int ic = k / 9, t = k % 9, kh = t / 3, kw = t % 3;
            int ih = oh * 2 - 1 + kh, iw = ow * 2 - 1 + kw;
            float v = 0.f;
            if (pxg < 196 && (unsigned)ih < 28u && (unsigned)iw < 28u)
                v = __ldg(inb + (size_t)ic * 784 + ih * 28 + iw);
            unsigned int h, l;
            tf32split(v, h, l);
            sBh[kl * 72 + pxl] = h;
            sBl[kl * 72 + pxl] = l;
        }
        __syncthreads();
#pragma unroll
        for (int ks = 0; ks < 4; ks++) {
            int kr = ks * 8;
            unsigned int ah0 = sAh[(kr + tig) * 72 + ocb + gid];
            unsigned int ah1 = sAh[(kr + tig) * 72 + ocb + gid + 8];
            unsigned int ah2 = sAh[(kr + tig + 4) * 72 + ocb + gid];
            unsigned int ah3 = sAh[(kr + tig + 4) * 72 + ocb + gid + 8];
            unsigned int al0 = sAl[(kr + tig) * 72 + ocb + gid];
            unsigned int al1 = sAl[(kr + tig) * 72 + ocb + gid + 8];
            unsigned int al2 = sAl[(kr + tig + 4) * 72 + ocb + gid];
            unsigned int al3 = sAl[(kr + tig + 4) * 72 + ocb + gid + 8];
#pragma unroll
            for (int nf = 0; nf < 8; nf++) {
                int col = nf * 8 + gid;
                unsigned int bh0 = sBh[(kr + tig) * 72 + col];
                unsigned int bh1 = sBh[(kr + tig + 4) * 72 + col];
                unsigned int bl0 = sBl[(kr + tig) * 72 + col];
                unsigned int bl1 = sBl[(kr + tig + 4) * 72 + col];
                MMA(acc[nf], ah0, ah1, ah2, ah3, bh0, bh1);
                MMA(acc[nf], ah0, ah1, ah2, ah3, bl0, bl1);
                MMA(acc[nf], al0, al1, al2, al3, bh0, bh1);
            }
        }
    }
    int r0 = ocz + ocb + gid, r1 = r0 + 8;
    float s0 = bg[r0] * rsqrtf(bv[r0] + 1e-5f);
    float h0 = (cb[r0] - bm[r0]) * s0 + bb[r0];
    float s1 = bg[r1] * rsqrtf(bv[r1] + 1e-5f);
    float h1 = (cb[r1] - bm[r1]) * s1 + bb[r1];
    float* o0 = g_a3 + ((size_t)b * 128 + r0) * 196;
    float* o1 = g_a3 + ((size_t)b * 128 + r1) * 196;
#pragma unroll
    for (int nf = 0; nf < 8; nf++) {
        int col = pxt + nf * 8 + 2 * tig;
        if (col + 1 < 196) {
            float2 v0 = make_float2(fmaxf(acc[nf][0] * s0 + h0, 0.f),
                                    fmaxf(acc[nf][1] * s0 + h0, 0.f));
            float2 v1 = make_float2(fmaxf(acc[nf][2] * s1 + h1, 0.f),
                                    fmaxf(acc[nf][3] * s1 + h1, 0.f));
            *reinterpret_cast<float2*>(o0 + col) = v0;
            *reinterpret_cast<float2*>(o1 + col) = v1;
        }
    }
}

// ---------------- adaptive avgpool (2,2): 14x14 -> 2x2 ----------------------
__global__ void pool_kernel() {
    int idx = blockIdx.x * 256 + threadIdx.x;
    if (idx >= 128 * 512) return;
    int b = idx >> 9;
    int r = idx & 511;
    int c = r >> 2;
    int ph = (r >> 1) & 1;
    int pw = r & 1;
    const float* src = g_a3 + (((size_t)b * 128 + c) * 14 + ph * 7) * 14 + pw * 7;
    float s = 0.f;
#pragma unroll
    for (int h = 0; h < 7; h++)
#pragma unroll
        for (int w = 0; w < 7; w++) s += src[h * 14 + w];
    g_feat[idx] = s * (1.f / 49.f);
}

// ---------------- head: linear->tanh, quantum circuit, MLP ------------------
__global__ void head_kernel(const float* __restrict__ pre_w, const float* __restrict__ pre_b,
                            const float* __restrict__ qw,
                            const float* __restrict__ pw1, const float* __restrict__ pb1,
                            const float* __restrict__ pw2, const float* __restrict__ pb2,
                            float* __restrict__ out) {
    __shared__ float f_s[512];
    __shared__ float ang_s[4], q_s[4], h1_s[64];
    const int tid = threadIdx.x;
    const int b = blockIdx.x;

    for (int i = tid; i < 512; i += 128) f_s[i] = g_feat[b * 512 + i];
    __syncthreads();

    int wid = tid >> 5, lane = tid & 31;
    {
        float partial = 0.f;
        const float* wr = pre_w + wid * 512;
        for (int k = lane; k < 512; k += 32) partial += f_s[k] * wr[k];
#pragma unroll
        for (int o = 16; o > 0; o >>= 1) partial += __shfl_down_sync(0xffffffffu, partial, o);
        if (lane == 0) ang_s[wid] = tanhf(partial + pre_b[wid]) * 3.14159265358979323846f;
    }
    __syncthreads();

    if (tid == 0) {
        float sr[16], si[16];
        float cq[4], sq[4];
#pragma unroll
        for (int q = 0; q < 4; q++) {
            cq[q] = cosf(0.5f * ang_s[q]);
            sq[q] = sinf(0.5f * ang_s[q]);
        }
#pragma unroll
        for (int i = 0; i < 16; i++) {
            float vv = 1.f;
#pragma unroll
            for (int q = 0; q < 4; q++) vv *= ((i >> (3 - q)) & 1) ? sq[q] : cq[q];
            sr[i] = vv;
            si[i] = 0.f;
        }
        for (int l = 0; l < 2; l++) {
            for (int q = 0; q < 4; q++) {
                const int mk = 1 << (3 - q);
                const float* qwp = qw + (l * 4 + q) * 3;
                float c, s;
                c = cosf(0.5f * qwp[0]); s = sinf(0.5f * qwp[0]);
                for (int i = 0; i < 16; i++)
                    if (!(i & mk)) {
                        int j = i | mk;
                        float r0 = sr[i], i0 = si[i], r1 = sr[j], i1 = si[j];
                        sr[i] = c * r0 + s * i1;  si[i] = c * i0 - s * r1;
                        sr[j] = c * r1 + s * i0;  si[j] = c * i1 - s * r0;
                    }
                c = cosf(0.5f * qwp[1]); s = sinf(0.5f * qwp[1]);
                for (int i = 0; i < 16; i++)
                    if (!(i & mk)) {
                        int j = i | mk;
                        float r0 = sr[i], i0 = si[i], r1 = sr[j], i1 = si[j];
                        sr[i] = c * r0 - s * r1;  si[i] = c * i0 - s * i1;
                        sr[j] = s * r0 + c * r1;  si[j] = s * i0 + c * i1;
                    }
                c = cosf(0.5f * qwp[2]); s = sinf(0.5f * qwp[2]);
                for (int i = 0; i < 16; i++) {
                    float r = sr[i], im = si[i];
                    if (i & mk) { sr[i] = c * r - s * im; si[i] = c * im + s * r; }
                    else        { sr[i] = c * r + s * im; si[i] = c * im - s * r; }
                }
            }
            for (int e = 0; e < 4; e++) {
                int cm = 1 << (3 - e);
                int tm = 1 << (3 - ((e + 1) & 3));
                for (int i = 0; i < 16; i++)
                    if ((i & cm) && !(i & tm)) {
                        int j = i | tm;
                        float t = sr[i]; sr[i] = sr[j]; sr[j] = t;
                        t = si[i]; si[i] = si[j]; si[j] = t;
                    }
            }
        }
        for (int q = 0; q < 4; q++) {
            float z = 0.f;
            for (int i = 0; i < 16; i++) {
                float pp = sr[i] * sr[i] + si[i] * si[i];
                z += ((i >> (3 - q)) & 1) ? -pp : pp;
            }
            q_s[q] = z;
        }
    }
    __syncthreads();

    if (tid < 64) {
        float h = pb1[tid];
#pragma unroll
        for (int j = 0; j < 4; j++) h += q_s[j] * pw1[tid * 4 + j];
        h1_s[tid] = fmaxf(h, 0.f);
    }
    __syncthreads();

    if (tid < 5) {
        float o = pb2[tid];
        for (int k = 0; k < 64; k++) o += h1_s[k] * pw2[tid * 64 + k];
        out[b * 5 + tid] = o;
    }
}

// ---------------- launch ----------------------------------------------------
extern "C" void kernel_launch(void* const* d_in, const int* in_sizes, int n_in,
                              void* d_out, int out_size) {
    const float* x    = (const float*)d_in[0];
    const float* c1w  = (const float*)d_in[1];
    const float* c1b  = (const float*)d_in[2];
    const float* bn1g = (const float*)d_in[3];
    const float* bn1b = (const float*)d_in[4];
    const float* bn1m = (const float*)d_in[5];
    const float* bn1v = (const float*)d_in[6];
    const float* c2w  = (const float*)d_in[7];
    const float* c2b  = (const float*)d_in[8];
    const float* bn2g = (const float*)d_in[9];
    const float* bn2b = (const float*)d_in[10];
    const float* bn2m = (const float*)d_in[11];
    const float* bn2v = (const float*)d_in[12];
    const float* c3w  = (const float*)d_in[13];
    const float* c3b  = (const float*)d_in[14];
    const float* bn3g = (const float*)d_in[15];
    const float* bn3b = (const float*)d_in[16];
    const float* bn3m = (const float*)d_in[17];
    const float* bn3v = (const float*)d_in[18];
    const float* pre_w = (const float*)d_in[19];
    const float* pre_b = (const float*)d_in[20];
    const float* qw    = (const float*)d_in[21];
    const float* pw1   = (const float*)d_in[22];
    const float* pb1   = (const float*)d_in[23];
    const float* pw2   = (const float*)d_in[24];
    const float* pb2   = (const float*)d_in[25];
    float* out = (float*)d_out;

    prep_w<<<288, 256>>>(c1w, c2w, c3w);
    conv1_mma<<<dim3(49, 128), 128>>>(x, bn1g, bn1b, bn1m, bn1v, c1b);
    conv2_mma<<<dim3(13, 128), 128>>>(bn2g, bn2b, bn2m, bn2v, c2b);
    conv3_mma<<<dim3(4, 128, 2), 128>>>(bn3g, bn3b, bn3m, bn3v, c3b);
    pool_kernel<<<256, 256>>>();
    head_kernel<<<128, 128>>>(pre_w, pre_b, qw, pw1, pb1, pw2, pb2, out);
}

// round 8
// speedup vs baseline: 1.2500x; 1.2500x over previous
#include <cuda_runtime.h>
#include <cuda_bf16.h>
#include <math.h>

// ---------------- intermediate buffers (device globals; no allocation) ------
__device__ float g_a1[128 * 32 * 56 * 56];   // conv1 out
__device__ float g_a2[128 * 64 * 28 * 28];   // conv2 out
__device__ float g_a3[128 * 128 * 14 * 14];  // conv3 out
__device__ float g_feat[128 * 512];          // pooled features

// packed tf32 weights: uint4 {hi(k0), lo(k0), hi(k0+4), lo(k0+4)}
// layout [chunk][ks][tig][oc], k0 = chunk*32 + ks*8 + tig
__device__ uint4 g_w1p[7 * 16 * 32];     // conv1: K=224 (kh*32 + kw*4 + ic, pads)
__device__ uint4 g_w2p[9 * 16 * 64];     // conv2: K=288 (tap*32 + ic)
__device__ uint4 g_w3p[18 * 16 * 128];   // conv3: K=576 (tap*64 + ic)

// ---------------- helpers ---------------------------------------------------
__device__ __forceinline__ void tf32split(float v, unsigned int& h, unsigned int& l) {
    asm("cvt.rna.tf32.f32 %0, %1;" : "=r"(h) : "f"(v));
    float r = v - __uint_as_float(h);
    asm("cvt.rna.tf32.f32 %0, %1;" : "=r"(l) : "f"(r));
}

#define MMA(d, A0, A1, A2, A3, B0, B1)                                          \
    asm volatile(                                                               \
        "mma.sync.aligned.m16n8k8.row.col.f32.tf32.tf32.f32 "                   \
        "{%0,%1,%2,%3}, {%4,%5,%6,%7}, {%8,%9}, {%0,%1,%2,%3};"                 \
        : "+f"(d[0]), "+f"(d[1]), "+f"(d[2]), "+f"(d[3])                        \
        : "r"(A0), "r"(A1), "r"(A2), "r"(A3), "r"(B0), "r"(B1))

// 3 MMAs (hi*hi + hi*lo + lo*hi) on a packed A pair + packed B
#define MMA3(acc, aL, aH, b4)                                                   \
    do {                                                                        \
        MMA(acc, aL.x, aH.x, aL.z, aH.z, b4.x, b4.z);                           \
        MMA(acc, aL.x, aH.x, aL.z, aH.z, b4.y, b4.w);                           \
        MMA(acc, aL.y, aH.y, aL.w, aH.w, b4.x, b4.z);                           \
    } while (0)

// ---------------- weight prep into packed layouts ---------------------------
__global__ void prep_w(const float* __restrict__ w1, const float* __restrict__ w2,
                       const float* __restrict__ w3) {
    int i = blockIdx.x * 256 + threadIdx.x;
    if (i < 7 * 16 * 32) {
        int oc = i & 31, row = (i >> 5) & 15, c = i >> 9;
        int ks = row >> 2, tig = row & 3;
        // k0: kh=c, kw=2ks, ic=tig ; k4: kw=2ks+1, ic=tig
        float v0 = (tig < 3) ? w1[oc * 147 + tig * 49 + c * 7 + 2 * ks] : 0.f;
        float v4 = (tig < 3 && 2 * ks + 1 < 7)
                       ? w1[oc * 147 + tig * 49 + c * 7 + 2 * ks + 1] : 0.f;
        uint4 r;
        tf32split(v0, r.x, r.y);
        tf32split(v4, r.z, r.w);
        g_w1p[i] = r;
    }
    if (i < 9 * 16 * 64) {
        int oc = i & 63, row = (i >> 6) & 15, c = i >> 10;
        int ks = row >> 2, tig = row & 3;
        int ic0 = ks * 8 + tig;  // tap = c
        float v0 = w2[oc * 288 + ic0 * 9 + c];
        float v4 = w2[oc * 288 + (ic0 + 4) * 9 + c];
        uint4 r;
        tf32split(v0, r.x, r.y);
        tf32split(v4, r.z, r.w);
        g_w2p[i] = r;
    }
    if (i < 18 * 16 * 128) {
        int oc = i & 127, row = (i >> 7) & 15, c = i >> 11;
        int ks = row >> 2, tig = row & 3;
        int t = c >> 1;
        int ic0 = (c & 1) * 32 + ks * 8 + tig;
        float v0 = w3[oc * 576 + ic0 * 9 + t];
        float v4 = w3[oc * 576 + (ic0 + 4) * 9 + t];
        uint4 r;
        tf32split(v0, r.x, r.y);
        tf32split(v4, r.z, r.w);
        g_w3p[i] = r;
    }
}

// ---------------- conv1: 3->32, 7x7 s4 p3, 224 -> 56 ------------------------
__global__ void conv1_mma(const float* __restrict__ x,
                          const float* __restrict__ bg, const float* __restrict__ bb,
                          const float* __restrict__ bm, const float* __restrict__ bv,
                          const float* __restrict__ cb) {
    __shared__ uint4 sA[16 * 34];   // [ks*4+tig][oc]
    __shared__ uint4 sB[16 * 130];  // [ks*4+tig][px]
    const int tid = threadIdx.x;
    const int b = blockIdx.y;
    const int pxt = blockIdx.x * 128;
    const int wid = tid >> 5, lane = tid & 31, gid = lane >> 2, tig = lane & 3;
    const int ocb = (wid & 1) * 16;
    const int pxw = (wid >> 1) * 32;

    float acc[4][4];
#pragma unroll
    for (int n = 0; n < 4; n++)
#pragma unroll
        for (int j = 0; j < 4; j++) acc[n][j] = 0.f;

    const int pxl = tid & 127;
    const int ksl = tid >> 7;  // 0..1
    const int pxg = pxt + pxl;
    const int oh = pxg / 56, ow = pxg % 56;
    const int ihb = oh * 4 - 3, iwb = ow * 4 - 3;
    const float* xb = x + (size_t)b * 3 * 50176;

    for (int c = 0; c < 7; c++) {  // chunk == kh
        __syncthreads();
#pragma unroll
        for (int i = 0; i < 2; i++) {
            int e = tid + i * 256;
            sA[(e >> 5) * 34 + (e & 31)] = g_w1p[c * 512 + e];
        }
        int ih = ihb + c;
        bool okh = (unsigned)ih < 224u;
        const float* xr = xb + ih * 224;
#pragma unroll
        for (int i = 0; i < 16; i++) {
            int kl = ksl * 16 + i;
            int kw = kl >> 2, ic = kl & 3;
            int iw = iwb + kw;
            float v = (ic < 3 && okh && (unsigned)iw < 224u)
                          ? __ldg(xr + ic * 50176 + iw) : 0.f;
            uint2 s;
            tf32split(v, s.x, s.y);
            int ks = kl >> 3, r = kl & 7, tg = r & 3, hf = r >> 2;
            ((uint2*)&sB[(ks * 4 + tg) * 130 + pxl])[hf] = s;
        }
        __syncthreads();
#pragma unroll
        for (int ks = 0; ks < 4; ks++) {
            const uint4* Ar = &sA[(ks * 4 + tig) * 34];
            const uint4* Br = &sB[(ks * 4 + tig) * 130];
            uint4 aL = Ar[ocb + gid], aH = Ar[ocb + gid + 8];
#pragma unroll
            for (int nf = 0; nf < 4; nf++) {
                uint4 b4 = Br[pxw + nf * 8 + gid];
                MMA3(acc[nf], aL, aH, b4);
            }
        }
    }
    int r0 = ocb + gid, r1 = r0 + 8;
    float s0 = bg[r0] * rsqrtf(bv[r0] + 1e-5f);
    float h0 = (cb[r0] - bm[r0]) * s0 + bb[r0];
    float s1 = bg[r1] * rsqrtf(bv[r1] + 1e-5f);
    float h1 = (cb[r1] - bm[r1]) * s1 + bb[r1];
    float* o0 = g_a1 + ((size_t)b * 32 + r0) * 3136;
    float* o1 = g_a1 + ((size_t)b * 32 + r1) * 3136;
#pragma unroll
    for (int nf = 0; nf < 4; nf++) {
        int col = pxt + pxw + nf * 8 + 2 * tig;
        if (col < 3136) {
            float2 v0 = make_float2(fmaxf(acc[nf][0] * s0 + h0, 0.f),
                                    fmaxf(acc[nf][1] * s0 + h0, 0.f));
            float2 v1 = make_float2(fmaxf(acc[nf][2] * s1 + h1, 0.f),
                                    fmaxf(acc[nf][3] * s1 + h1, 0.f));
            *reinterpret_cast<float2*>(o0 + col) = v0;
            *reinterpret_cast<float2*>(o1 + col) = v1;
        }
    }
}

// ---------------- conv2: 32->64, 3x3 s2 p1, 56 -> 28 ------------------------
__global__ void conv2_mma(const float* __restrict__ bg, const float* __restrict__ bb,
                          const float* __restrict__ bm, const float* __restrict__ bv,
                          const float* __restrict__ cb) {
    __shared__ uint4 sA[16 * 66];
    __shared__ uint4 sB[16 * 66];
    const int tid = threadIdx.x;
    const int b = blockIdx.y;
    const int pxt = blockIdx.x * 64;
    const int wid = tid >> 5, lane = tid & 31, gid = lane >> 2, tig = lane & 3;
    const int ocb = (wid & 3) * 16;
    const int pxw = (wid >> 2) * 32;

    float acc[4][4];
#pragma unroll
    for (int n = 0; n < 4; n++)
#pragma unroll
        for (int j = 0; j < 4; j++) acc[n][j] = 0.f;

    const int pxl = tid & 63;
    const int ksl = tid >> 6;  // 0..3
    const int pxg = pxt + pxl;
    const int oh = pxg / 28, ow = pxg % 28;
    const int ihb = oh * 2 - 1, iwb = ow * 2 - 1;
    const float* inb = g_a1 + (size_t)b * 32 * 3136;

    for (int c = 0; c < 9; c++) {  // chunk == tap
        int kh = (c * 11) >> 5;
        int kw = c - kh * 3;
        int ih = ihb + kh, iw = iwb + kw;
        bool okc = (unsigned)ih < 56u && (unsigned)iw < 56u;
        const float* src = inb + ih * 56 + iw;
        __syncthreads();
#pragma unroll
        for (int i = 0; i < 4; i++) {
            int e = tid + i * 256;
            sA[(e >> 6) * 66 + (e & 63)] = g_w2p[c * 1024 + e];
        }
#pragma unroll
        for (int i = 0; i < 8; i++) {
            int kl = ksl * 8 + i;  // ic = kl
            float v = okc ? __ldg(src + kl * 3136) : 0.f;
            uint2 s;
            tf32split(v, s.x, s.y);
            int ks = kl >> 3, r = kl & 7, tg = r & 3, hf = r >> 2;
            ((uint2*)&sB[(ks * 4 + tg) * 66 + pxl])[hf] = s;
        }
        __syncthreads();
#pragma unroll
        for (int ks = 0; ks < 4; ks++) {
            const uint4* Ar = &sA[(ks * 4 + tig) * 66];
            const uint4* Br = &sB[(ks * 4 + tig) * 66];
            uint4 aL = Ar[ocb + gid], aH = Ar[ocb + gid + 8];
#pragma unroll
            for (int nf = 0; nf < 4; nf++) {
                uint4 b4 = Br[pxw + nf * 8 + gid];
                MMA3(acc[nf], aL, aH, b4);
            }
        }
    }
    int r0 = ocb + gid, r1 = r0 + 8;
    float s0 = bg[r0] * rsqrtf(bv[r0] + 1e-5f);
    float h0 = (cb[r0] - bm[r0]) * s0 + bb[r0];
    float s1 = bg[r1] * rsqrtf(bv[r1] + 1e-5f);
    float h1 = (cb[r1] - bm[r1]) * s1 + bb[r1];
    float* o0 = g_a2 + ((size_t)b * 64 + r0) * 784;
    float* o1 = g_a2 + ((size_t)b * 64 + r1) * 784;
#pragma unroll
    for (int nf = 0; nf < 4; nf++) {
        int col = pxt + pxw + nf * 8 + 2 * tig;
        if (col < 784) {
            float2 v0 = make_float2(fmaxf(acc[nf][0] * s0 + h0, 0.f),
                                    fmaxf(acc[nf][1] * s0 + h0, 0.f));
            float2 v1 = make_float2(fmaxf(acc[nf][2] * s1 + h1, 0.f),
                                    fmaxf(acc[nf][3] * s1 + h1, 0.f));
            *reinterpret_cast<float2*>(o0 + col) = v0;
            *reinterpret_cast<float2*>(o1 + col) = v1;
        }
    }
}

// ---------------- conv3: 64->128, 3x3 s2 p1, 28 -> 14 -----------------------
__global__ void conv3_mma(const float* __restrict__ bg, const float* __restrict__ bb,
                          const float* __restrict__ bm, const float* __restrict__ bv,
                          const float* __restrict__ cb) {
    __shared__ uint4 sA[16 * 66];
    __shared__ uint4 sB[16 * 66];
    const int tid = threadIdx.x;
    const int b = blockIdx.y;
    const int pxt = blockIdx.x * 64;
    const int ocz = blockIdx.z * 64;
    const int wid = tid >> 5, lane = tid & 31, gid = lane >> 2, tig = lane & 3;
    const int ocb = (wid & 3) * 16;
    const int pxw = (wid >> 2) * 32;

    float acc[4][4];
#pragma unroll
    for (int n = 0; n < 4; n++)
#pragma unroll
        for (int j = 0; j < 4; j++) acc[n][j] = 0.f;

    const int pxl = tid & 63;
    const int ksl = tid >> 6;
    const int pxg = pxt + pxl;
    const int oh = pxg / 14, ow = pxg % 14;
    const int ihb = oh * 2 - 1, iwb = ow * 2 - 1;
    const float* inb = g_a2 + (size_t)b * 64 * 784;

    for (int c = 0; c < 18; c++) {  // tap = c>>1, ic base = (c&1)*32
        int t = c >> 1;
        int kh = (t * 11) >> 5;
        int kw = t - kh * 3;
        int ih = ihb + kh, iw = iwb + kw;
        bool okc = (unsigned)ih < 28u && (unsigned)iw < 28u;
        const float* src = inb + ((c & 1) * 32) * 784 + ih * 28 + iw;
        __syncthreads();
#pragma unroll
        for (int i = 0; i < 4; i++) {
            int e = tid + i * 256;
            sA[(e >> 6) * 66 + (e & 63)] = g_w3p[(c * 16 + (e >> 6)) * 128 + ocz + (e & 63)];
        }
#pragma unroll
        for (int i = 0; i < 8; i++) {
            int kl = ksl * 8 + i;
            float v = okc ? __ldg(src + kl * 784) : 0.f;
            uint2 s;
            tf32split(v, s.x, s.y);
            int ks = kl >> 3, r = kl & 7, tg = r & 3, hf = r >> 2;
            ((uint2*)&sB[(ks * 4 + tg) * 66 + pxl])[hf] = s;
        }
        __syncthreads();
#pragma unroll
        for (int ks = 0; ks < 4; ks++) {
            const uint4* Ar = &sA[(ks * 4 + tig) * 66];
            const uint4* Br = &sB[(ks * 4 + tig) * 66];
            uint4 aL = Ar[ocb + gid], aH = Ar[ocb + gid + 8];
#pragma unroll
            for (int nf = 0; nf < 4; nf++) {
                uint4 b4 = Br[pxw + nf * 8 + gid];
                MMA3(acc[nf], aL, aH, b4);
            }
        }
    }
    int r0 = ocz + ocb + gid, r1 = r0 + 8;
    float s0 = bg[r0] * rsqrtf(bv[r0] + 1e-5f);
    float h0 = (cb[r0] - bm[r0]) * s0 + bb[r0];
    float s1 = bg[r1] * rsqrtf(bv[r1] + 1e-5f);
    float h1 = (cb[r1] - bm[r1]) * s1 + bb[r1];
    float* o0 = g_a3 + ((size_t)b * 128 + r0) * 196;
    float* o1 = g_a3 + ((size_t)b * 128 + r1) * 196;
#pragma unroll
    for (int nf = 0; nf < 4; nf++) {
        int col = pxt + pxw + nf * 8 + 2 * tig;
        if (col < 196) {
            float2 v0 = make_float2(fmaxf(acc[nf][0] * s0 + h0, 0.f),
                                    fmaxf(acc[nf][1] * s0 + h0, 0.f));
            float2 v1 = make_float2(fmaxf(acc[nf][2] * s1 + h1, 0.f),
                                    fmaxf(acc[nf][3] * s1 + h1, 0.f));
            *reinterpret_cast<float2*>(o0 + col) = v0;
            *reinterpret_cast<float2*>(o1 + col) = v1;
        }
    }
}

// ---------------- adaptive avgpool (2,2): 14x14 -> 2x2 ----------------------
__global__ void pool_kernel() {
    int idx = blockIdx.x * 256 + threadIdx.x;
    if (idx >= 128 * 512) return;
    int b = idx >> 9;
    int r = idx & 511;
    int c = r >> 2;
    int ph = (r >> 1) & 1;
    int pw = r & 1;
    const float* src = g_a3 + (((size_t)b * 128 + c) * 14 + ph * 7) * 14 + pw * 7;
    float s = 0.f;
#pragma unroll
    for (int h = 0; h < 7; h++)
#pragma unroll
        for (int w = 0; w < 7; w++) s += src[h * 14 + w];
    g_feat[idx] = s * (1.f / 49.f);
}

// ---------------- head: linear->tanh, quantum circuit, MLP ------------------
__global__ void head_kernel(const float* __restrict__ pre_w, const float* __restrict__ pre_b,
                            const float* __restrict__ qw,
                            const float* __restrict__ pw1, const float* __restrict__ pb1,
                            const float* __restrict__ pw2, const float* __restrict__ pb2,
                            float* __restrict__ out) {
    __shared__ float f_s[512];
    __shared__ float ang_s[4], q_s[4], h1_s[64];
    const int tid = threadIdx.x;
    const int b = blockIdx.x;

    for (int i = tid; i < 512; i += 128) f_s[i] = g_feat[b * 512 + i];
    __syncthreads();

    int wid = tid >> 5, lane = tid & 31;
    {
        float partial = 0.f;
        const float* wr = pre_w + wid * 512;
        for (int k = lane; k < 512; k += 32) partial += f_s[k] * wr[k];
#pragma unroll
        for (int o = 16; o > 0; o >>= 1) partial += __shfl_down_sync(0xffffffffu, partial, o);
        if (lane == 0) ang_s[wid] = tanhf(partial + pre_b[wid]) * 3.14159265358979323846f;
    }
    __syncthreads();

    if (tid == 0) {
        float sr[16], si[16];
        float cq[4], sq[4];
#pragma unroll
        for (int q = 0; q < 4; q++) {
            cq[q] = cosf(0.5f * ang_s[q]);
            sq[q] = sinf(0.5f * ang_s[q]);
        }
#pragma unroll
        for (int i = 0; i < 16; i++) {
            float vv = 1.f;
#pragma unroll
            for (int q = 0; q < 4; q++) vv *= ((i >> (3 - q)) & 1) ? sq[q] : cq[q];
            sr[i] = vv;
            si[i] = 0.f;
        }
        for (int l = 0; l < 2; l++) {
            for (int q = 0; q < 4; q++) {
                const int mk = 1 << (3 - q);
                const float* qwp = qw + (l * 4 + q) * 3;
                float c, s;
                c = cosf(0.5f * qwp[0]); s = sinf(0.5f * qwp[0]);
                for (int i = 0; i < 16; i++)
                    if (!(i & mk)) {
                        int j = i | mk;
                        float r0 = sr[i], i0 = si[i], r1 = sr[j], i1 = si[j];
                        sr[i] = c * r0 + s * i1;  si[i] = c * i0 - s * r1;
                        sr[j] = c * r1 + s * i0;  si[j] = c * i1 - s * r0;
                    }
                c = cosf(0.5f * qwp[1]); s = sinf(0.5f * qwp[1]);
                for (int i = 0; i < 16; i++)
                    if (!(i & mk)) {
                        int j = i | mk;
                        float r0 = sr[i], i0 = si[i], r1 = sr[j], i1 = si[j];
                        sr[i] = c * r0 - s * r1;  si[i] = c * i0 - s * i1;
                        sr[j] = s * r0 + c * r1;  si[j] = s * i0 + c * i1;
                    }
                c = cosf(0.5f * qwp[2]); s = sinf(0.5f * qwp[2]);
                for (int i = 0; i < 16; i++) {
                    float r = sr[i], im = si[i];
                    if (i & mk) { sr[i] = c * r - s * im; si[i] = c * im + s * r; }
                    else        { sr[i] = c * r + s * im; si[i] = c * im - s * r; }
                }
            }
            for (int e = 0; e < 4; e++) {
                int cm = 1 << (3 - e);
                int tm = 1 << (3 - ((e + 1) & 3));
                for (int i = 0; i < 16; i++)
                    if ((i & cm) && !(i & tm)) {
                        int j = i | tm;
                        float t = sr[i]; sr[i] = sr[j]; sr[j] = t;
                        t = si[i]; si[i] = si[j]; si[j] = t;
                    }
            }
        }
        for (int q = 0; q < 4; q++) {
            float z = 0.f;
            for (int i = 0; i < 16; i++) {
                float pp = sr[i] * sr[i] + si[i] * si[i];
                z += ((i >> (3 - q)) & 1) ? -pp : pp;
            }
            q_s[q] = z;
        }
    }
    __syncthreads();

    if (tid < 64) {
        float h = pb1[tid];
#pragma unroll
        for (int j = 0; j < 4; j++) h += q_s[j] * pw1[tid * 4 + j];
        h1_s[tid] = fmaxf(h, 0.f);
    }
    __syncthreads();

    if (tid < 5) {
        float o = pb2[tid];
        for (int k = 0; k < 64; k++) o += h1_s[k] * pw2[tid * 64 + k];
        out[b * 5 + tid] = o;
    }
}

// ---------------- launch ----------------------------------------------------
extern "C" void kernel_launch(void* const* d_in, const int* in_sizes, int n_in,
                              void* d_out, int out_size) {
    const float* x    = (const float*)d_in[0];
    const float* c1w  = (const float*)d_in[1];
    const float* c1b  = (const float*)d_in[2];
    const float* bn1g = (const float*)d_in[3];
    const float* bn1b = (const float*)d_in[4];
    const float* bn1m = (const float*)d_in[5];
    const float* bn1v = (const float*)d_in[6];
    const float* c2w  = (const float*)d_in[7];
    const float* c2b  = (const float*)d_in[8];
    const float* bn2g = (const float*)d_in[9];
    const float* bn2b = (const float*)d_in[10];
    const float* bn2m = (const float*)d_in[11];
    const float* bn2v = (const float*)d_in[12];
    const float* c3w  = (const float*)d_in[13];
    const float* c3b  = (const float*)d_in[14];
    const float* bn3g = (const float*)d_in[15];
    const float* bn3b = (const float*)d_in[16];
    const float* bn3m = (const float*)d_in[17];
    const float* bn3v = (const float*)d_in[18];
    const float* pre_w = (const float*)d_in[19];
    const float* pre_b = (const float*)d_in[20];
    const float* qw    = (const float*)d_in[21];
    const float* pw1   = (const float*)d_in[22];
    const float* pb1   = (const float*)d_in[23];
    const float* pw2   = (const float*)d_in[24];
    const float* pb2   = (const float*)d_in[25];
    float* out = (float*)d_out;

    prep_w<<<144, 256>>>(c1w, c2w, c3w);
    conv1_mma<<<dim3(25, 128), 256>>>(x, bn1g, bn1b, bn1m, bn1v, c1b);
    conv2_mma<<<dim3(13, 128), 256>>>(bn2g, bn2b, bn2m, bn2v, c2b);
    conv3_mma<<<dim3(4, 128, 2), 256>>>(bn3g, bn3b, bn3m, bn3v, c3b);
    pool_kernel<<<256, 256>>>();
    head_kernel<<<128, 128>>>(pre_w, pre_b, qw, pw1, pb1, pw2, pb2, out);
}